// round 2
// baseline (speedup 1.0000x reference)
#include <cuda_runtime.h>
#include <cstdint>

#define BATCHN 64
#define SEQN   512
#define EMBN   256
#define HN     256
#define G4N    1024   // 4*H
#define NCOL   2048   // both directions' gate columns
#define NLAB   10

// ---------------- scratch (device globals; no runtime allocation) ----------
__device__ float g_zx[(size_t)SEQN * BATCHN * NCOL];   // [t][b][col2]  (268 MB)
__device__ float g_h[2][2][HN][BATCHN];                // [dir][buf][unit][batch]
__device__ unsigned int          g_bar_count;          // zero-init, self-resetting
__device__ volatile unsigned int g_bar_gen;

// ---------------- f32x2 helpers -------------------------------------------
__device__ __forceinline__ uint64_t pack2(float lo, float hi) {
    uint64_t r;
    asm("mov.b64 %0, {%1, %2};" : "=l"(r)
        : "r"(__float_as_uint(lo)), "r"(__float_as_uint(hi)));
    return r;
}
__device__ __forceinline__ void unpack2(uint64_t v, float& lo, float& hi) {
    unsigned a, b;
    asm("mov.b64 {%0, %1}, %2;" : "=r"(a), "=r"(b) : "l"(v));
    lo = __uint_as_float(a); hi = __uint_as_float(b);
}
__device__ __forceinline__ uint64_t ffma2(uint64_t a, uint64_t b, uint64_t c) {
    uint64_t d;
    asm("fma.rn.f32x2 %0, %1, %2, %3;" : "=l"(d) : "l"(a), "l"(b), "l"(c));
    return d;
}

__device__ __forceinline__ float sigf(float x) {
    return __fdividef(1.0f, 1.0f + __expf(-x));
}
__device__ __forceinline__ float tanhfast(float x) {
    // tanh(x) = 1 - 2/(exp(2x)+1); robust at both extremes with __expf
    float e = __expf(2.0f * x);
    return 1.0f - 2.0f * __fdividef(1.0f, e + 1.0f);
}

// ============================================================================
// Kernel 1: zx = gather(emb, tokens) @ [Wx_f || Wx_b] + [b_f || b_b]
// GEMM M=32768 (t*64+b), N=2048, K=256.  CTA tile 128x64, K-chunks of 64.
// Thread tile 8(M)x4(N) via f32x2 packed over M-pairs.
// ============================================================================
__global__ void __launch_bounds__(256) zx_gemm_kernel(
    const int*   __restrict__ tokens,
    const float* __restrict__ emb,
    const float* __restrict__ Wx_f, const float* __restrict__ b_f,
    const float* __restrict__ Wx_b, const float* __restrict__ b_b)
{
    __shared__ float a_s[64][128];   // [k][m]  32 KB
    __shared__ float b_s[64][64];    // [k][n]  16 KB

    const int tid   = threadIdx.x;
    const int mtile = blockIdx.x >> 5;   // 0..255  (consecutive bids share mtile? no:
    const int ntile = blockIdx.x & 31;   //  consecutive bids share mtile -> A reuse in L2)

    // ---- A staging assignment: 128 rows x 2 k-halves
    const int mrow  = tid & 127;
    const int khalf = tid >> 7;                       // 0/1 -> 32 k each
    const int gm    = mtile * 128 + mrow;             // global m = t*64+b
    const int tok   = tokens[(gm & 63) * SEQN + (gm >> 6)];
    const float* arow = emb + (size_t)tok * EMBN + khalf * 32;

    // ---- B staging assignment: 64 rows x 4 segs of 16 floats
    const int brow   = tid >> 2;
    const int bseg   = tid & 3;
    const int n2base = ntile * 64;
    const float* wsrc = (n2base < G4N) ? (Wx_f + n2base) : (Wx_b + (n2base - G4N));

    const int m0  = (tid & 15) * 8;   // local m base (8 consecutive rows)
    const int n0l = (tid >> 4) * 4;   // local n base (4 consecutive cols)

    uint64_t acc[4][4];
#pragma unroll
    for (int i = 0; i < 4; ++i)
#pragma unroll
        for (int j = 0; j < 4; ++j) acc[i][j] = 0ull;   // {0.f,0.f}

    for (int kc = 0; kc < 4; ++kc) {
        const int kbase = kc * 64;
        // stage A (transpose to [k][m])
#pragma unroll
        for (int i = 0; i < 8; ++i) {
            float4 v = *(const float4*)(arow + kbase + i * 4);
            a_s[khalf * 32 + i * 4 + 0][mrow] = v.x;
            a_s[khalf * 32 + i * 4 + 1][mrow] = v.y;
            a_s[khalf * 32 + i * 4 + 2][mrow] = v.z;
            a_s[khalf * 32 + i * 4 + 3][mrow] = v.w;
        }
        // stage B (straight copy)
#pragma unroll
        for (int i = 0; i < 4; ++i) {
            float4 v = *(const float4*)(wsrc + (size_t)(kbase + brow) * G4N + bseg * 16 + i * 4);
            *(float4*)&b_s[brow][bseg * 16 + i * 4] = v;
        }
        __syncthreads();

#pragma unroll 8
        for (int k = 0; k < 64; ++k) {
            ulonglong2 a01 = *(const ulonglong2*)&a_s[k][m0];
            ulonglong2 a23 = *(const ulonglong2*)&a_s[k][m0 + 4];
            float4 bv = *(const float4*)&b_s[k][n0l];
            uint64_t bb0 = pack2(bv.x, bv.x);
            uint64_t bb1 = pack2(bv.y, bv.y);
            uint64_t bb2 = pack2(bv.z, bv.z);
            uint64_t bb3 = pack2(bv.w, bv.w);
            acc[0][0] = ffma2(a01.x, bb0, acc[0][0]);
            acc[0][1] = ffma2(a01.x, bb1, acc[0][1]);
            acc[0][2] = ffma2(a01.x, bb2, acc[0][2]);
            acc[0][3] = ffma2(a01.x, bb3, acc[0][3]);
            acc[1][0] = ffma2(a01.y, bb0, acc[1][0]);
            acc[1][1] = ffma2(a01.y, bb1, acc[1][1]);
            acc[1][2] = ffma2(a01.y, bb2, acc[1][2]);
            acc[1][3] = ffma2(a01.y, bb3, acc[1][3]);
            acc[2][0] = ffma2(a23.x, bb0, acc[2][0]);
            acc[2][1] = ffma2(a23.x, bb1, acc[2][1]);
            acc[2][2] = ffma2(a23.x, bb2, acc[2][2]);
            acc[2][3] = ffma2(a23.x, bb3, acc[2][3]);
            acc[3][0] = ffma2(a23.y, bb0, acc[3][0]);
            acc[3][1] = ffma2(a23.y, bb1, acc[3][1]);
            acc[3][2] = ffma2(a23.y, bb2, acc[3][2]);
            acc[3][3] = ffma2(a23.y, bb3, acc[3][3]);
        }
        __syncthreads();
    }

    // epilogue: + bias, store two rows per acc row-pair
    float bias[4];
#pragma unroll
    for (int i = 0; i < 4; ++i) {
        int col2 = n2base + n0l + i;
        bias[i] = (col2 < G4N) ? b_f[col2] : b_b[col2 - G4N];
    }
#pragma unroll
    for (int mp = 0; mp < 4; ++mp) {
        float4 vlo, vhi;
        unpack2(acc[mp][0], vlo.x, vhi.x);
        unpack2(acc[mp][1], vlo.y, vhi.y);
        unpack2(acc[mp][2], vlo.z, vhi.z);
        unpack2(acc[mp][3], vlo.w, vhi.w);
        vlo.x += bias[0]; vlo.y += bias[1]; vlo.z += bias[2]; vlo.w += bias[3];
        vhi.x += bias[0]; vhi.y += bias[1]; vhi.z += bias[2]; vhi.w += bias[3];
        size_t r = (size_t)(mtile * 128 + m0 + 2 * mp) * NCOL + n2base + n0l;
        *(float4*)(g_zx + r)        = vlo;
        *(float4*)(g_zx + r + NCOL) = vhi;
    }
}

// ============================================================================
// Kernel 2: persistent bidirectional LSTM recurrence.
// 128 CTAs x 128 threads. dir = bid>>6, CTA owns 4 hidden units.
// Thread = (batch-pair bp, unit-local ul). f32x2 packed over the batch pair.
// Grid barrier between steps (all CTAs co-resident: 128 <= 148 SMs).
// ============================================================================
__device__ __forceinline__ void grid_barrier() {
    __syncthreads();
    if (threadIdx.x == 0) {
        __threadfence();
        unsigned gen = g_bar_gen;
        if (atomicAdd(&g_bar_count, 1u) == gridDim.x - 1u) {
            g_bar_count = 0;
            __threadfence();
            g_bar_gen = gen + 1u;
        } else {
            while (g_bar_gen == gen) { __nanosleep(32); }
        }
        __threadfence();
    }
    __syncthreads();
}

__global__ void __launch_bounds__(128) lstm_kernel(
    const float* __restrict__ Wh_f, const float* __restrict__ Wh_b)
{
    extern __shared__ unsigned char smraw[];
    float (*h_s)[BATCHN] = (float(*)[BATCHN])smraw;           // [256][64]  64 KB
    uint64_t* wh2 = (uint64_t*)(smraw + HN * BATCHN * 4);     // [j][ul][gate] dup'd, 32 KB

    const int tid = threadIdx.x;
    const int dir = blockIdx.x >> 6;
    const int cid = blockIdx.x & 63;
    const int u0  = cid * 4;
    const float* Wh = dir ? Wh_b : Wh_f;

    // stage duplicated Wh pairs once: wh2[j*16 + ul*4 + g] = {w,w}
    for (int idx = tid; idx < HN * 16; idx += 128) {
        int j  = idx >> 4;
        int ul = (idx >> 2) & 3;
        int g  = idx & 3;
        float w = Wh[j * G4N + g * HN + u0 + ul];
        wh2[idx] = pack2(w, w);
    }
    __syncthreads();

    const int bp = tid >> 2;
    const int ul = tid & 3;
    const int b0 = bp * 2;
    const int u  = u0 + ul;
    const uint64_t* wp = wh2 + ul * 4;

    float c0 = 0.0f, c1 = 0.0f;

    for (int t = 0; t < SEQN; ++t) {
        const int zt = dir ? (SEQN - 1 - t) : t;
        const float* zrow = g_zx + ((size_t)zt * BATCHN + b0) * NCOL + dir * G4N + u;
        // preload zx gate pre-activations (independent of h -> hides HBM latency)
        float zi0 = __ldg(zrow + 0 * HN), zf0 = __ldg(zrow + 1 * HN);
        float zg0 = __ldg(zrow + 2 * HN), zo0 = __ldg(zrow + 3 * HN);
        float zi1 = __ldg(zrow + NCOL + 0 * HN), zf1 = __ldg(zrow + NCOL + 1 * HN);
        float zg1 = __ldg(zrow + NCOL + 2 * HN), zo1 = __ldg(zrow + NCOL + 3 * HN);
        uint64_t ai = pack2(zi0, zi1);
        uint64_t af = pack2(zf0, zf1);
        uint64_t ag = pack2(zg0, zg1);
        uint64_t ao = pack2(zo0, zo1);

        if (t > 0) {
            // stage h_prev (written by all CTAs last step) via L2 (bypass stale L1)
            const float4* src = (const float4*)&g_h[dir][t & 1][0][0];
            float4* dst = (float4*)h_s;
#pragma unroll
            for (int i = 0; i < 32; ++i)
                dst[tid + i * 128] = __ldcg(src + tid + i * 128);
            __syncthreads();

#pragma unroll 8
            for (int j = 0; j < HN; ++j) {
                uint64_t h2 = *(const uint64_t*)&h_s[j][b0];
                ulonglong2 w01 = *(const ulonglong2*)(wp + j * 16);
                ulonglong2 w23 = *(const ulonglong2*)(wp + j * 16 + 2);
                ai = ffma2(h2, w01.x, ai);
                af = ffma2(h2, w01.y, af);
                ag = ffma2(h2, w23.x, ag);
                ao = ffma2(h2, w23.y, ao);
            }
        }

        float i0, i1, f0, f1, g0, g1, o0, o1;
        unpack2(ai, i0, i1); unpack2(af, f0, f1);
        unpack2(ag, g0, g1); unpack2(ao, o0, o1);

        float I0 = sigf(i0), F0 = sigf(f0), Gt0 = tanhfast(g0), O0 = sigf(o0);
        float I1 = sigf(i1), F1 = sigf(f1), Gt1 = tanhfast(g1), O1 = sigf(o1);
        c0 = F0 * c0 + I0 * Gt0;
        c1 = F1 * c1 + I1 * Gt1;
        float h0 = O0 * tanhfast(c0);
        float h1 = O1 * tanhfast(c1);

        *(float2*)&g_h[dir][(t + 1) & 1][u][b0] = make_float2(h0, h1);

        grid_barrier();
    }
}

// ============================================================================
// Kernel 3: logits = [h_fwd, h_bwd] @ W_out + b_out, then softmax.
// ============================================================================
__global__ void __launch_bounds__(256) out_kernel(
    const float* __restrict__ W_out, const float* __restrict__ b_out,
    float* __restrict__ out)
{
    __shared__ float ws[2 * HN * NLAB];   // 20 KB
    const int tid = threadIdx.x;
    for (int i = tid; i < 2 * HN * NLAB; i += 256) ws[i] = W_out[i];
    __syncthreads();

    if (tid < BATCHN) {
        const int b = tid;
        float acc[NLAB];
#pragma unroll
        for (int l = 0; l < NLAB; ++l) acc[l] = b_out[l];
        for (int u = 0; u < HN; ++u) {
            float hv = g_h[0][0][u][b];
#pragma unroll
            for (int l = 0; l < NLAB; ++l) acc[l] += hv * ws[u * NLAB + l];
        }
        for (int u = 0; u < HN; ++u) {
            float hv = g_h[1][0][u][b];
#pragma unroll
            for (int l = 0; l < NLAB; ++l) acc[l] += hv * ws[(HN + u) * NLAB + l];
        }
        float m = acc[0];
#pragma unroll
        for (int l = 1; l < NLAB; ++l) m = fmaxf(m, acc[l]);
        float s = 0.0f;
#pragma unroll
        for (int l = 0; l < NLAB; ++l) { acc[l] = expf(acc[l] - m); s += acc[l]; }
        float inv = 1.0f / s;
#pragma unroll
        for (int l = 0; l < NLAB; ++l) out[b * NLAB + l] = acc[l] * inv;
    }
}

// ============================================================================
extern "C" void kernel_launch(void* const* d_in, const int* in_sizes, int n_in,
                              void* d_out, int out_size)
{
    const int*   tokens = (const int*)  d_in[0];
    const float* emb    = (const float*)d_in[1];
    const float* Wx_f   = (const float*)d_in[2];
    const float* Wh_f   = (const float*)d_in[3];
    const float* b_f    = (const float*)d_in[4];
    const float* Wx_b   = (const float*)d_in[5];
    const float* Wh_b   = (const float*)d_in[6];
    const float* b_b    = (const float*)d_in[7];
    const float* W_out  = (const float*)d_in[8];
    const float* b_out  = (const float*)d_in[9];
    float* out = (float*)d_out;

    const int lstm_smem = HN * BATCHN * 4 + HN * 16 * 8;   // 64KB + 32KB = 98304
    cudaFuncSetAttribute(lstm_kernel,
                         cudaFuncAttributeMaxDynamicSharedMemorySize, lstm_smem);

    zx_gemm_kernel<<<8192, 256>>>(tokens, emb, Wx_f, b_f, Wx_b, b_b);
    lstm_kernel<<<128, 128, lstm_smem>>>(Wh_f, Wh_b);
    out_kernel<<<1, 256>>>(W_out, b_out, out);
}